// round 5
// baseline (speedup 1.0000x reference)
#include <cuda_runtime.h>
#include <cuda_fp16.h>
#include <cstdint>
#include <cstddef>

#define TOK 8192
#define DIN 4096
#define DOUT 4096
#define RANK 16
#define NBLK (DIN / 64)
#define K_EXT 4160            // DIN + 64 (16 lora cols + 1 bias col + pad)
#define SCALING 4.0f          // 16 / sqrt(16)

#define BM 128
#define BN 128
#define BK 64
#define NSTAGE 3
#define KITER (K_EXT / BK)    // 65

#define ROWB 144                             // 128B data + 16B pad; conflict-free ldmatrix
#define A_BYTES (BM * ROWB)                  // 18432
#define B_BYTES (BN * ROWB)                  // 18432
#define STAGE_BYTES (A_BYTES + B_BYTES)      // 36864
#define SMEM_TOTAL (NSTAGE * STAGE_BYTES)    // 110592 -> 2 CTAs/SM

#define NT_TILES (DOUT / BN)                 // 32
#define MT_TILES (TOK / BM)                  // 64

// Extended operand buffers (static device scratch; no runtime allocation)
__device__ __align__(1024) __half g_A[(size_t)TOK * K_EXT];   // ~68 MB
__device__ __align__(1024) __half g_B[(size_t)DOUT * K_EXT];  // ~34 MB

__constant__ float c_nf4[16] = {
    -1.0f, -0.6961928009986877f, -0.5250730514526367f, -0.39491748809814453f,
    -0.28444138169288635f, -0.18477343022823334f, -0.09105003625154495f, 0.0f,
    0.07958029955625534f, 0.16093020141124725f, 0.24611230194568634f,
    0.33791524171829224f, 0.44070982933044434f, 0.5626170039176941f,
    0.7229568362236023f, 1.0f};

// ---------------------------------------------------------------- helpers
__device__ __forceinline__ uint32_t s2u(const void* p) {
    uint32_t a;
    asm("{ .reg .u64 t; cvta.to.shared.u64 t, %1; cvt.u32.u64 %0, t; }"
        : "=r"(a) : "l"(p));
    return a;
}
__device__ __forceinline__ void cp16(uint32_t s, const void* g) {
    asm volatile("cp.async.cg.shared.global [%0], [%1], 16;" :: "r"(s), "l"(g));
}
__device__ __forceinline__ void cp_commit() {
    asm volatile("cp.async.commit_group;" ::: "memory");
}
__device__ __forceinline__ void ldsm4(uint32_t addr, uint32_t& r0, uint32_t& r1,
                                      uint32_t& r2, uint32_t& r3) {
    asm volatile("ldmatrix.sync.aligned.m8n8.x4.shared.b16 {%0,%1,%2,%3}, [%4];"
                 : "=r"(r0), "=r"(r1), "=r"(r2), "=r"(r3) : "r"(addr));
}
__device__ __forceinline__ void mma16816(float* c, const uint32_t* a,
                                         const uint32_t* b) {
    asm volatile(
        "mma.sync.aligned.m16n8k16.row.col.f32.f16.f16.f32 "
        "{%0,%1,%2,%3}, {%4,%5,%6,%7}, {%8,%9}, {%0,%1,%2,%3};"
        : "+f"(c[0]), "+f"(c[1]), "+f"(c[2]), "+f"(c[3])
        : "r"(a[0]), "r"(a[1]), "r"(a[2]), "r"(a[3]), "r"(b[0]), "r"(b[1]));
}

// -------------------------------------------------------- fused prep kernel
// blocks [0, DOUT): NF4 dequant -> g_B (+ lora_B cols, bias, zeros)
// blocks [DOUT, DOUT + TOK/8): x -> fp16 g_A + u = x@lora_A (fused, x read once)
__global__ void __launch_bounds__(256) prep_all(
    const float* __restrict__ x, const int* __restrict__ wc,
    const float* __restrict__ am, const float* __restrict__ bias,
    const float* __restrict__ la, const float* __restrict__ lb) {
    __shared__ float sA[512 * 18];  // 36 KB (only used by the xu path)
    int tid = threadIdx.x;

    if (blockIdx.x < DOUT) {
        // ---------------- prep_w path ----------------
        int n = blockIdx.x;
        const int* wr = wc + (size_t)n * DIN;
        __half* br = g_B + (size_t)n * K_EXT;
        const float* amr = am + (size_t)n * NBLK;
        for (int k4 = tid; k4 < DIN / 4; k4 += 256) {
            int k = k4 * 4;
            int4 c = ((const int4*)wr)[k4];
            float s = amr[k >> 6];
            __half2 h0 = __floats2half2_rn(c_nf4[c.x] * s, c_nf4[c.y] * s);
            __half2 h1 = __floats2half2_rn(c_nf4[c.z] * s, c_nf4[c.w] * s);
            ((__half2*)br)[k4 * 2] = h0;
            ((__half2*)br)[k4 * 2 + 1] = h1;
        }
        if (tid < RANK) br[DIN + tid] = __float2half(SCALING * lb[(size_t)tid * DOUT + n]);
        else if (tid == RANK) br[DIN + RANK] = __float2half(bias[n]);
        else if (tid < 64) br[DIN + tid] = __float2half(0.0f);
        return;
    }

    // ---------------- prep_xu path: 8 token rows per block, 1 warp each ----
    int wid = tid >> 5, lane = tid & 31;
    size_t m = (size_t)(blockIdx.x - DOUT) * 8 + wid;
    const float* xr = x + m * DIN;
    __half* ar = g_A + m * K_EXT;
    float acc[16];
#pragma unroll
    for (int r = 0; r < 16; r++) acc[r] = 0.0f;

    for (int kc = 0; kc < DIN; kc += 512) {
        __syncthreads();
        const float4* la4 = (const float4*)(la + (size_t)kc * 16);
        for (int i = tid; i < 2048; i += 256) {
            float4 v = la4[i];
            float* d = sA + (i >> 2) * 18 + (i & 3) * 4;
            ((float2*)d)[0] = make_float2(v.x, v.y);
            ((float2*)d)[1] = make_float2(v.z, v.w);
        }
        __syncthreads();
#pragma unroll 4
        for (int ki = 0; ki < 16; ki++) {
            int k = ki * 32 + lane;
            float xv = xr[kc + k];
            ar[kc + k] = __float2half(xv);
            const float* ap = sA + k * 18;
#pragma unroll
            for (int q = 0; q < 8; q++) {
                float2 p = ((const float2*)ap)[q];
                acc[2 * q] += xv * p.x;
                acc[2 * q + 1] += xv * p.y;
            }
        }
    }
#pragma unroll
    for (int r = 0; r < 16; r++) {
        acc[r] += __shfl_xor_sync(0xffffffffu, acc[r], 16);
        acc[r] += __shfl_xor_sync(0xffffffffu, acc[r], 8);
        acc[r] += __shfl_xor_sync(0xffffffffu, acc[r], 4);
        acc[r] += __shfl_xor_sync(0xffffffffu, acc[r], 2);
        acc[r] += __shfl_xor_sync(0xffffffffu, acc[r], 1);
    }
    if (lane == 0) {
#pragma unroll
        for (int r = 0; r < 16; r++) ar[DIN + r] = __float2half(acc[r]);
    }
    ar[DIN + 16 + lane] = __float2half(lane == 0 ? 1.0f : 0.0f);
    if (lane < 16) ar[DIN + 48 + lane] = __float2half(0.0f);
}

// -------------------------------------------------------- main GEMM
// out[TOK, DOUT] = A_ext @ B_extᵀ via mma.sync.m16n8k16 (fp16 in, fp32 acc).
// 128 threads = 4 warps (2x2 of 64x64 warptiles), 2 CTAs/SM.
// Cross-k16 fragment double-buffering hides ldsm latency under HMMA bursts.
__global__ void __launch_bounds__(128, 2) qlora_gemm(float* __restrict__ out) {
    extern __shared__ char smem[];
    uint32_t sb = s2u(smem);
    int tid = threadIdx.x, wid = tid >> 5, lane = tid & 31;
    int warp_m = wid & 1, warp_n = wid >> 1;   // 2 x 2

    // L2-banded CTA order: 8 m-tiles x 32 n-tiles per band (256 CTAs/band)
    int bid = (int)blockIdx.x;
    int band = bid >> 8;
    int local = bid & 255;
    int mt = band * 8 + (local & 7);   // 0..63
    int nt = local >> 3;               // 0..31

    // cp.async: 128 threads, 8 x 16B chunks per row-group of 16 rows
    const __half* sA0 = g_A + (size_t)mt * BM * K_EXT +
                        (size_t)(tid >> 3) * K_EXT + (tid & 7) * 8;
    const __half* sB0 = g_B + (size_t)nt * BN * K_EXT +
                        (size_t)(tid >> 3) * K_EXT + (tid & 7) * 8;
    uint32_t dA0 = (uint32_t)(tid >> 3) * ROWB + (tid & 7) * 16;
    uint32_t dB0 = A_BYTES + dA0;

    uint32_t aLdBase = (warp_m * 64 + (lane & 15)) * ROWB + (lane >> 4) * 16;
    uint32_t bLdBase = A_BYTES +
        (warp_n * 64 + ((lane >> 4) & 1) * 8 + (lane & 7)) * ROWB +
        ((lane >> 3) & 1) * 16;

    float acc[4][8][4];
#pragma unroll
    for (int mi = 0; mi < 4; mi++)
#pragma unroll
        for (int ni = 0; ni < 8; ni++)
#pragma unroll
            for (int j = 0; j < 4; j++) acc[mi][ni][j] = 0.0f;

#define ISSUE_STAGE(stage, kiter)                                              \
    {                                                                          \
        uint32_t base_ = sb + (stage) * STAGE_BYTES;                           \
        int k0_ = (kiter) * BK;                                                \
        _Pragma("unroll")                                                      \
        for (int i = 0; i < 8; i++)                                            \
            cp16(base_ + dA0 + i * (16 * ROWB),                                \
                 sA0 + k0_ + (size_t)i * 16 * K_EXT);                          \
        _Pragma("unroll")                                                      \
        for (int i = 0; i < 8; i++)                                            \
            cp16(base_ + dB0 + i * (16 * ROWB),                                \
                 sB0 + k0_ + (size_t)i * 16 * K_EXT);                          \
    }

#define LOAD_FRAGS(buf, aB, bB, kOff)                                          \
    {                                                                          \
        _Pragma("unroll")                                                      \
        for (int mi = 0; mi < 4; mi++)                                         \
            ldsm4((aB) + mi * (16 * ROWB) + (kOff),                            \
                  a[buf][mi][0], a[buf][mi][1], a[buf][mi][2], a[buf][mi][3]); \
        _Pragma("unroll")                                                      \
        for (int nj = 0; nj < 4; nj++)                                         \
            ldsm4((bB) + nj * (16 * ROWB) + (kOff),                            \
                  b[buf][2 * nj][0], b[buf][2 * nj][1],                        \
                  b[buf][2 * nj + 1][0], b[buf][2 * nj + 1][1]);               \
    }

    // ---- prologue: fill 2 stages ----
    ISSUE_STAGE(0, 0); cp_commit();
    ISSUE_STAGE(1, 1); cp_commit();

    int s = 0, sn = 2;
    for (int it = 0; it < KITER; ++it) {
        asm volatile("cp.async.wait_group %0;" :: "n"(1) : "memory");
        __syncthreads();

        // prefetch next stage immediately (overlaps with MMA below)
        if (it + 2 < KITER) ISSUE_STAGE(sn, it + 2);
        cp_commit();

        uint32_t aB = sb + s * STAGE_BYTES + aLdBase;
        uint32_t bB = sb + s * STAGE_BYTES + bLdBase;

        uint32_t a[2][4][4], b[2][8][2];
        LOAD_FRAGS(0, aB, bB, 0);

#pragma unroll
        for (int kh = 0; kh < 4; kh++) {      // four k16 steps per BK=64
            int cur = kh & 1, nxb = cur ^ 1;
            if (kh < 3) LOAD_FRAGS(nxb, aB, bB, (kh + 1) * 32);
#pragma unroll
            for (int mi = 0; mi < 4; mi++)
#pragma unroll
                for (int ni = 0; ni < 8; ni++)
                    mma16816(acc[mi][ni], a[cur][mi], b[cur][ni]);
        }

        s = (s == 2) ? 0 : s + 1;
        sn = (sn == 2) ? 0 : sn + 1;
    }

    // ---- epilogue: registers -> global fp32 ----
    int m0 = mt * BM + warp_m * 64 + (lane >> 2);
    int n0 = nt * BN + warp_n * 64 + (lane & 3) * 2;
#pragma unroll
    for (int mi = 0; mi < 4; mi++) {
#pragma unroll
        for (int ni = 0; ni < 8; ni++) {
            float* p0 = out + (size_t)(m0 + mi * 16) * DOUT + n0 + ni * 8;
            float* p1 = p0 + 8 * DOUT;
            *(float2*)p0 = make_float2(acc[mi][ni][0], acc[mi][ni][1]);
            *(float2*)p1 = make_float2(acc[mi][ni][2], acc[mi][ni][3]);
        }
    }
}

// -------------------------------------------------------- launch
extern "C" void kernel_launch(void* const* d_in, const int* in_sizes, int n_in,
                              void* d_out, int out_size) {
    const float* x = (const float*)d_in[0];
    const int* wc = (const int*)d_in[1];
    const float* am = (const float*)d_in[2];
    const float* bias = (const float*)d_in[3];
    const float* la = (const float*)d_in[4];
    const float* lb = (const float*)d_in[5];
    float* out = (float*)d_out;

    cudaFuncSetAttribute(qlora_gemm, cudaFuncAttributeMaxDynamicSharedMemorySize,
                         SMEM_TOTAL);

    prep_all<<<DOUT + TOK / 8, 256>>>(x, wc, am, bias, la, lb);
    qlora_gemm<<<MT_TILES * NT_TILES, 128, SMEM_TOTAL>>>(out);
}

// round 7
// speedup vs baseline: 1.1738x; 1.1738x over previous
#include <cuda_runtime.h>
#include <cuda_fp16.h>
#include <cstdint>
#include <cstddef>

#define TOK 8192
#define DIN 4096
#define DOUT 4096
#define RANK 16
#define NBLK (DIN / 64)
#define K_EXT 4160            // DIN + 64 (16 lora cols + 1 bias col + pad)
#define SCALING 4.0f          // 16 / sqrt(16)

#define BM 128
#define BN 128
#define BK 64
#define NSTAGE 3
#define KITER (K_EXT / BK)    // 65

#define ROWB 144                             // 128B data + 16B pad; conflict-free ldmatrix
#define A_BYTES (BM * ROWB)                  // 18432
#define B_BYTES (BN * ROWB)                  // 18432
#define STAGE_BYTES (A_BYTES + B_BYTES)      // 36864
#define SMEM_TOTAL (NSTAGE * STAGE_BYTES)    // 110592 -> 2 CTAs/SM

#define NT_TILES (DOUT / BN)                 // 32
#define MT_TILES (TOK / BM)                  // 64

// Extended operand buffers (static device scratch; no runtime allocation)
__device__ __align__(1024) __half g_A[(size_t)TOK * K_EXT];   // ~68 MB
__device__ __align__(1024) __half g_B[(size_t)DOUT * K_EXT];  // ~34 MB

__constant__ float c_nf4[16] = {
    -1.0f, -0.6961928009986877f, -0.5250730514526367f, -0.39491748809814453f,
    -0.28444138169288635f, -0.18477343022823334f, -0.09105003625154495f, 0.0f,
    0.07958029955625534f, 0.16093020141124725f, 0.24611230194568634f,
    0.33791524171829224f, 0.44070982933044434f, 0.5626170039176941f,
    0.7229568362236023f, 1.0f};

// ---------------------------------------------------------------- helpers
__device__ __forceinline__ uint32_t s2u(const void* p) {
    uint32_t a;
    asm("{ .reg .u64 t; cvta.to.shared.u64 t, %1; cvt.u32.u64 %0, t; }"
        : "=r"(a) : "l"(p));
    return a;
}
__device__ __forceinline__ void cp16(uint32_t s, const void* g) {
    asm volatile("cp.async.cg.shared.global [%0], [%1], 16;" :: "r"(s), "l"(g));
}
__device__ __forceinline__ void cp_commit() {
    asm volatile("cp.async.commit_group;" ::: "memory");
}
__device__ __forceinline__ void ldsm4(uint32_t addr, uint32_t& r0, uint32_t& r1,
                                      uint32_t& r2, uint32_t& r3) {
    asm volatile("ldmatrix.sync.aligned.m8n8.x4.shared.b16 {%0,%1,%2,%3}, [%4];"
                 : "=r"(r0), "=r"(r1), "=r"(r2), "=r"(r3) : "r"(addr));
}
__device__ __forceinline__ void mma16816(float* c, const uint32_t* a,
                                         const uint32_t* b) {
    asm volatile(
        "mma.sync.aligned.m16n8k16.row.col.f32.f16.f16.f32 "
        "{%0,%1,%2,%3}, {%4,%5,%6,%7}, {%8,%9}, {%0,%1,%2,%3};"
        : "+f"(c[0]), "+f"(c[1]), "+f"(c[2]), "+f"(c[3])
        : "r"(a[0]), "r"(a[1]), "r"(a[2]), "r"(a[3]), "r"(b[0]), "r"(b[1]));
}

// -------------------------------------------------------- fused prep kernel
// blocks [0, DOUT): NF4 dequant -> g_B (+ lora_B cols, bias, zeros)
// blocks [DOUT, DOUT + TOK/8): x -> fp16 g_A + u = x@lora_A (fused, x read once)
__global__ void __launch_bounds__(256) prep_all(
    const float* __restrict__ x, const int* __restrict__ wc,
    const float* __restrict__ am, const float* __restrict__ bias,
    const float* __restrict__ la, const float* __restrict__ lb) {
    __shared__ float sA[512 * 18];  // 36 KB (only used by the xu path)
    int tid = threadIdx.x;
    int lane = tid & 31;

    if (blockIdx.x < DOUT) {
        // ---------------- prep_w path ----------------
        // Register LUT + shfl: each lane holds c_nf4[lane&15]; codebook lookup
        // becomes a single shfl.idx (no constant-cache divergent replay).
        float lutv = c_nf4[lane & 15];
        int n = blockIdx.x;
        const int* wr = wc + (size_t)n * DIN;
        __half* br = g_B + (size_t)n * K_EXT;
        const float* amr = am + (size_t)n * NBLK;
        for (int k4 = tid; k4 < DIN / 4; k4 += 256) {
            int k = k4 * 4;
            int4 c = ((const int4*)wr)[k4];
            float s = amr[k >> 6];
            float v0 = __shfl_sync(0xffffffffu, lutv, c.x & 15);
            float v1 = __shfl_sync(0xffffffffu, lutv, c.y & 15);
            float v2 = __shfl_sync(0xffffffffu, lutv, c.z & 15);
            float v3 = __shfl_sync(0xffffffffu, lutv, c.w & 15);
            __half2 h0 = __floats2half2_rn(v0 * s, v1 * s);
            __half2 h1 = __floats2half2_rn(v2 * s, v3 * s);
            ((__half2*)br)[k4 * 2] = h0;
            ((__half2*)br)[k4 * 2 + 1] = h1;
        }
        if (tid < RANK) br[DIN + tid] = __float2half(SCALING * lb[(size_t)tid * DOUT + n]);
        else if (tid == RANK) br[DIN + RANK] = __float2half(bias[n]);
        else if (tid < 64) br[DIN + tid] = __float2half(0.0f);
        return;
    }

    // ---------------- prep_xu path: 8 token rows per block, 1 warp each ----
    int wid = tid >> 5;
    size_t m = (size_t)(blockIdx.x - DOUT) * 8 + wid;
    const float* xr = x + m * DIN;
    __half* ar = g_A + m * K_EXT;
    float acc[16];
#pragma unroll
    for (int r = 0; r < 16; r++) acc[r] = 0.0f;

    for (int kc = 0; kc < DIN; kc += 512) {
        __syncthreads();
        const float4* la4 = (const float4*)(la + (size_t)kc * 16);
        for (int i = tid; i < 2048; i += 256) {
            float4 v = la4[i];
            float* d = sA + (i >> 2) * 18 + (i & 3) * 4;
            ((float2*)d)[0] = make_float2(v.x, v.y);
            ((float2*)d)[1] = make_float2(v.z, v.w);
        }
        __syncthreads();
        // 2 consecutive k per lane: float2 load, half2 store, both coalesced
#pragma unroll 4
        for (int ki = 0; ki < 8; ki++) {
            int k = ki * 64 + lane * 2;
            float2 xv = *(const float2*)(xr + kc + k);
            *(__half2*)(ar + kc + k) = __floats2half2_rn(xv.x, xv.y);
            const float* ap0 = sA + k * 18;
            const float* ap1 = ap0 + 18;
#pragma unroll
            for (int q = 0; q < 8; q++) {
                float2 p0 = ((const float2*)ap0)[q];
                float2 p1 = ((const float2*)ap1)[q];
                acc[2 * q] += xv.x * p0.x + xv.y * p1.x;
                acc[2 * q + 1] += xv.x * p0.y + xv.y * p1.y;
            }
        }
    }
#pragma unroll
    for (int r = 0; r < 16; r++) {
        acc[r] += __shfl_xor_sync(0xffffffffu, acc[r], 16);
        acc[r] += __shfl_xor_sync(0xffffffffu, acc[r], 8);
        acc[r] += __shfl_xor_sync(0xffffffffu, acc[r], 4);
        acc[r] += __shfl_xor_sync(0xffffffffu, acc[r], 2);
        acc[r] += __shfl_xor_sync(0xffffffffu, acc[r], 1);
    }
    if (lane == 0) {
#pragma unroll
        for (int r = 0; r < 16; r++) ar[DIN + r] = __float2half(acc[r]);
    }
    ar[DIN + 16 + lane] = __float2half(lane == 0 ? 1.0f : 0.0f);
    if (lane < 16) ar[DIN + 48 + lane] = __float2half(0.0f);
}

// -------------------------------------------------------- main GEMM
// out[TOK, DOUT] = A_ext @ B_extᵀ via mma.sync.m16n8k16 (fp16 in, fp32 acc).
// 128 threads = 4 warps (2x2 of 64x64 warptiles), 2 CTAs/SM.
// cp.async issue is split into 4 chunks interleaved with the 4 k16 MMA blocks
// so the LSU burst never starves the tensor pipe.
__global__ void __launch_bounds__(128, 2) qlora_gemm(float* __restrict__ out) {
    extern __shared__ char smem[];
    uint32_t sb = s2u(smem);
    int tid = threadIdx.x, wid = tid >> 5, lane = tid & 31;
    int warp_m = wid & 1, warp_n = wid >> 1;   // 2 x 2

    // L2-banded CTA order: 8 m-tiles x 32 n-tiles per band (256 CTAs/band)
    int bid = (int)blockIdx.x;
    int band = bid >> 8;
    int local = bid & 255;
    int mt = band * 8 + (local & 7);   // 0..63
    int nt = local >> 3;               // 0..31

    // cp.async: 128 threads, 8 x 16B chunks per row-group of 16 rows
    const __half* sA0 = g_A + (size_t)mt * BM * K_EXT +
                        (size_t)(tid >> 3) * K_EXT + (tid & 7) * 8;
    const __half* sB0 = g_B + (size_t)nt * BN * K_EXT +
                        (size_t)(tid >> 3) * K_EXT + (tid & 7) * 8;
    uint32_t dA0 = (uint32_t)(tid >> 3) * ROWB + (tid & 7) * 16;
    uint32_t dB0 = A_BYTES + dA0;

    uint32_t aLdBase = (warp_m * 64 + (lane & 15)) * ROWB + (lane >> 4) * 16;
    uint32_t bLdBase = A_BYTES +
        (warp_n * 64 + ((lane >> 4) & 1) * 8 + (lane & 7)) * ROWB +
        ((lane >> 3) & 1) * 16;

    float acc[4][8][4];
#pragma unroll
    for (int mi = 0; mi < 4; mi++)
#pragma unroll
        for (int ni = 0; ni < 8; ni++)
#pragma unroll
            for (int j = 0; j < 4; j++) acc[mi][ni][j] = 0.0f;

#define ISSUE_STAGE(stage, kiter)                                              \
    {                                                                          \
        uint32_t base_ = sb + (stage) * STAGE_BYTES;                           \
        int k0_ = (kiter) * BK;                                                \
        _Pragma("unroll")                                                      \
        for (int i = 0; i < 8; i++)                                            \
            cp16(base_ + dA0 + i * (16 * ROWB),                                \
                 sA0 + k0_ + (size_t)i * 16 * K_EXT);                          \
        _Pragma("unroll")                                                      \
        for (int i = 0; i < 8; i++)                                            \
            cp16(base_ + dB0 + i * (16 * ROWB),                                \
                 sB0 + k0_ + (size_t)i * 16 * K_EXT);                          \
    }

    // Chunk ch (0..3): A row-groups {2ch, 2ch+1} + B row-groups {2ch, 2ch+1}
    // = 4 cp16 per chunk; the 4 chunks exactly cover all 16 per-thread cp16.
#define ISSUE_CHUNK(stage, kiter, ch)                                          \
    {                                                                          \
        uint32_t base_ = sb + (stage) * STAGE_BYTES;                           \
        int k0_ = (kiter) * BK;                                                \
        _Pragma("unroll")                                                      \
        for (int i = 2 * (ch); i < 2 * (ch) + 2; i++) {                        \
            cp16(base_ + dA0 + i * (16 * ROWB),                                \
                 sA0 + k0_ + (size_t)i * 16 * K_EXT);                          \
            cp16(base_ + dB0 + i * (16 * ROWB),                                \
                 sB0 + k0_ + (size_t)i * 16 * K_EXT);                          \
        }                                                                      \
    }

#define LOAD_FRAGS(buf, aB, bB, kOff)                                          \
    {                                                                          \
        _Pragma("unroll")                                                      \
        for (int mi = 0; mi < 4; mi++)                                         \
            ldsm4((aB) + mi * (16 * ROWB) + (kOff),                            \
                  a[buf][mi][0], a[buf][mi][1], a[buf][mi][2], a[buf][mi][3]); \
        _Pragma("unroll")                                                      \
        for (int nj = 0; nj < 4; nj++)                                         \
            ldsm4((bB) + nj * (16 * ROWB) + (kOff),                            \
                  b[buf][2 * nj][0], b[buf][2 * nj][1],                        \
                  b[buf][2 * nj + 1][0], b[buf][2 * nj + 1][1]);               \
    }

    // ---- prologue: fill 2 stages ----
    ISSUE_STAGE(0, 0); cp_commit();
    ISSUE_STAGE(1, 1); cp_commit();

    int s = 0, sn = 2;
    for (int it = 0; it < KITER; ++it) {
        asm volatile("cp.async.wait_group %0;" :: "n"(1) : "memory");
        __syncthreads();

        uint32_t aB = sb + s * STAGE_BYTES + aLdBase;
        uint32_t bB = sb + s * STAGE_BYTES + bLdBase;
        bool pf = (it + 2 < KITER);

        uint32_t a[2][4][4], b[2][8][2];
        LOAD_FRAGS(0, aB, bB, 0);

#pragma unroll
        for (int kh = 0; kh < 4; kh++) {      // four k16 steps per BK=64
            int cur = kh & 1, nxb = cur ^ 1;
            if (kh < 3) LOAD_FRAGS(nxb, aB, bB, (kh + 1) * 32);
            // interleave 1/4 of next-stage cp.async with this MMA block
            if (pf) { ISSUE_CHUNK(sn, it + 2, kh); }
#pragma unroll
            for (int mi = 0; mi < 4; mi++)
#pragma unroll
                for (int ni = 0; ni < 8; ni++)
                    mma16816(acc[mi][ni], a[cur][mi], b[cur][ni]);
        }
        cp_commit();

        s = (s == 2) ? 0 : s + 1;
        sn = (sn == 2) ? 0 : sn + 1;
    }

    // ---- epilogue: registers -> global fp32 ----
    int m0 = mt * BM + warp_m * 64 + (lane >> 2);
    int n0 = nt * BN + warp_n * 64 + (lane & 3) * 2;
#pragma unroll
    for (int mi = 0; mi < 4; mi++) {
#pragma unroll
        for (int ni = 0; ni < 8; ni++) {
            float* p0 = out + (size_t)(m0 + mi * 16) * DOUT + n0 + ni * 8;
            float* p1 = p0 + 8 * DOUT;
            *(float2*)p0 = make_float2(acc[mi][ni][0], acc[mi][ni][1]);
            *(float2*)p1 = make_float2(acc[mi][ni][2], acc[mi][ni][3]);
        }
    }
}

// -------------------------------------------------------- launch
extern "C" void kernel_launch(void* const* d_in, const int* in_sizes, int n_in,
                              void* d_out, int out_size) {
    const float* x = (const float*)d_in[0];
    const int* wc = (const int*)d_in[1];
    const float* am = (const float*)d_in[2];
    const float* bias = (const float*)d_in[3];
    const float* la = (const float*)d_in[4];
    const float* lb = (const float*)d_in[5];
    float* out = (float*)d_out;

    cudaFuncSetAttribute(qlora_gemm, cudaFuncAttributeMaxDynamicSharedMemorySize,
                         SMEM_TOTAL);

    prep_all<<<DOUT + TOK / 8, 256>>>(x, wc, am, bias, la, lb);
    qlora_gemm<<<MT_TILES * NT_TILES, 128, SMEM_TOTAL>>>(out);
}

// round 8
// speedup vs baseline: 1.2865x; 1.0960x over previous
#include <cuda_runtime.h>
#include <cuda_fp16.h>
#include <cstdint>
#include <cstddef>

#define TOK 8192
#define DIN 4096
#define DOUT 4096
#define RANK 16
#define NBLK (DIN / 64)
#define K_EXT 4160            // DIN + 64 (16 lora cols + 1 bias col + pad)
#define SCALING 4.0f          // 16 / sqrt(16)

#define BM 128
#define BN 128
#define BK 64
#define NSTAGE 3
#define KITER (K_EXT / BK)    // 65

#define ROWB 144                             // 128B data + 16B pad; conflict-free ldmatrix
#define A_BYTES (BM * ROWB)                  // 18432
#define B_BYTES (BN * ROWB)                  // 18432
#define STAGE_BYTES (A_BYTES + B_BYTES)      // 36864
#define SMEM_TOTAL (NSTAGE * STAGE_BYTES)    // 110592 -> 2 CTAs/SM

#define NT_TILES (DOUT / BN)                 // 32
#define MT_TILES (TOK / BM)                  // 64

// Extended operand buffers (static device scratch; no runtime allocation)
__device__ __align__(1024) __half g_A[(size_t)TOK * K_EXT];   // ~68 MB
__device__ __align__(1024) __half g_B[(size_t)DOUT * K_EXT];  // ~34 MB

__constant__ float c_nf4[16] = {
    -1.0f, -0.6961928009986877f, -0.5250730514526367f, -0.39491748809814453f,
    -0.28444138169288635f, -0.18477343022823334f, -0.09105003625154495f, 0.0f,
    0.07958029955625534f, 0.16093020141124725f, 0.24611230194568634f,
    0.33791524171829224f, 0.44070982933044434f, 0.5626170039176941f,
    0.7229568362236023f, 1.0f};

// ---------------------------------------------------------------- helpers
__device__ __forceinline__ uint32_t s2u(const void* p) {
    uint32_t a;
    asm("{ .reg .u64 t; cvta.to.shared.u64 t, %1; cvt.u32.u64 %0, t; }"
        : "=r"(a) : "l"(p));
    return a;
}
__device__ __forceinline__ void cp16(uint32_t s, const void* g) {
    asm volatile("cp.async.cg.shared.global [%0], [%1], 16;" :: "r"(s), "l"(g));
}
__device__ __forceinline__ void cp_commit() {
    asm volatile("cp.async.commit_group;" ::: "memory");
}
__device__ __forceinline__ void ldsm4(uint32_t addr, uint32_t& r0, uint32_t& r1,
                                      uint32_t& r2, uint32_t& r3) {
    asm volatile("ldmatrix.sync.aligned.m8n8.x4.shared.b16 {%0,%1,%2,%3}, [%4];"
                 : "=r"(r0), "=r"(r1), "=r"(r2), "=r"(r3) : "r"(addr));
}
__device__ __forceinline__ void mma16816(float* c, const uint32_t* a,
                                         const uint32_t* b) {
    asm volatile(
        "mma.sync.aligned.m16n8k16.row.col.f32.f16.f16.f32 "
        "{%0,%1,%2,%3}, {%4,%5,%6,%7}, {%8,%9}, {%0,%1,%2,%3};"
        : "+f"(c[0]), "+f"(c[1]), "+f"(c[2]), "+f"(c[3])
        : "r"(a[0]), "r"(a[1]), "r"(a[2]), "r"(a[3]), "r"(b[0]), "r"(b[1]));
}

// -------------------------------------------------------- fused prep kernel
// blocks [0, DOUT): NF4 dequant -> g_B (+ lora_B cols, bias, zeros)
// blocks [DOUT, DOUT + TOK/16): x -> fp16 g_A + u = x@lora_A, 2 rows per warp
__global__ void __launch_bounds__(256) prep_all(
    const float* __restrict__ x, const int* __restrict__ wc,
    const float* __restrict__ am, const float* __restrict__ bias,
    const float* __restrict__ la, const float* __restrict__ lb) {
    __shared__ float sA[512 * 18];  // 36 KB (only used by the xu path)
    int tid = threadIdx.x;
    int lane = tid & 31;

    if (blockIdx.x < DOUT) {
        // ---------------- prep_w path ----------------
        // Register LUT + shfl: codebook lookup = 1 shfl.idx, no const-cache replay
        float lutv = c_nf4[lane & 15];
        int n = blockIdx.x;
        const int* wr = wc + (size_t)n * DIN;
        __half* br = g_B + (size_t)n * K_EXT;
        const float* amr = am + (size_t)n * NBLK;
        for (int k4 = tid; k4 < DIN / 4; k4 += 256) {
            int k = k4 * 4;
            int4 c = ((const int4*)wr)[k4];
            float s = amr[k >> 6];
            float v0 = __shfl_sync(0xffffffffu, lutv, c.x & 15);
            float v1 = __shfl_sync(0xffffffffu, lutv, c.y & 15);
            float v2 = __shfl_sync(0xffffffffu, lutv, c.z & 15);
            float v3 = __shfl_sync(0xffffffffu, lutv, c.w & 15);
            __half2 h0 = __floats2half2_rn(v0 * s, v1 * s);
            __half2 h1 = __floats2half2_rn(v2 * s, v3 * s);
            ((__half2*)br)[k4 * 2] = h0;
            ((__half2*)br)[k4 * 2 + 1] = h1;
        }
        if (tid < RANK) br[DIN + tid] = __float2half(SCALING * lb[(size_t)tid * DOUT + n]);
        else if (tid == RANK) br[DIN + RANK] = __float2half(bias[n]);
        else if (tid < 64) br[DIN + tid] = __float2half(0.0f);
        return;
    }

    // ------------- prep_xu path: 16 rows/block, 2 rows per warp -------------
    // Each loaded lora_A float2 is reused for both rows: halves LDS traffic/row.
    int wid = tid >> 5;
    size_t m0 = (size_t)(blockIdx.x - DOUT) * 16 + wid * 2;
    const float* xr0 = x + m0 * DIN;
    const float* xr1 = xr0 + DIN;
    __half* ar0 = g_A + m0 * K_EXT;
    __half* ar1 = ar0 + K_EXT;
    float acc[2][16];
#pragma unroll
    for (int r = 0; r < 16; r++) { acc[0][r] = 0.0f; acc[1][r] = 0.0f; }

    for (int kc = 0; kc < DIN; kc += 512) {
        __syncthreads();
        const float4* la4 = (const float4*)(la + (size_t)kc * 16);
        for (int i = tid; i < 2048; i += 256) {
            float4 v = la4[i];
            float* d = sA + (i >> 2) * 18 + (i & 3) * 4;
            ((float2*)d)[0] = make_float2(v.x, v.y);
            ((float2*)d)[1] = make_float2(v.z, v.w);
        }
        __syncthreads();
#pragma unroll 4
        for (int ki = 0; ki < 8; ki++) {
            int k = ki * 64 + lane * 2;
            float2 xv0 = *(const float2*)(xr0 + kc + k);
            float2 xv1 = *(const float2*)(xr1 + kc + k);
            *(__half2*)(ar0 + kc + k) = __floats2half2_rn(xv0.x, xv0.y);
            *(__half2*)(ar1 + kc + k) = __floats2half2_rn(xv1.x, xv1.y);
            const float* ap0 = sA + k * 18;
            const float* ap1 = ap0 + 18;
#pragma unroll
            for (int q = 0; q < 8; q++) {
                float2 p0 = ((const float2*)ap0)[q];
                float2 p1 = ((const float2*)ap1)[q];
                acc[0][2 * q]     += xv0.x * p0.x + xv0.y * p1.x;
                acc[0][2 * q + 1] += xv0.x * p0.y + xv0.y * p1.y;
                acc[1][2 * q]     += xv1.x * p0.x + xv1.y * p1.x;
                acc[1][2 * q + 1] += xv1.x * p0.y + xv1.y * p1.y;
            }
        }
    }
#pragma unroll
    for (int rr = 0; rr < 2; rr++)
#pragma unroll
        for (int r = 0; r < 16; r++) {
            acc[rr][r] += __shfl_xor_sync(0xffffffffu, acc[rr][r], 16);
            acc[rr][r] += __shfl_xor_sync(0xffffffffu, acc[rr][r], 8);
            acc[rr][r] += __shfl_xor_sync(0xffffffffu, acc[rr][r], 4);
            acc[rr][r] += __shfl_xor_sync(0xffffffffu, acc[rr][r], 2);
            acc[rr][r] += __shfl_xor_sync(0xffffffffu, acc[rr][r], 1);
        }
    if (lane == 0) {
#pragma unroll
        for (int r = 0; r < 16; r++) {
            ar0[DIN + r] = __float2half(acc[0][r]);
            ar1[DIN + r] = __float2half(acc[1][r]);
        }
    }
    ar0[DIN + 16 + lane] = __float2half(lane == 0 ? 1.0f : 0.0f);
    ar1[DIN + 16 + lane] = __float2half(lane == 0 ? 1.0f : 0.0f);
    if (lane < 16) {
        ar0[DIN + 48 + lane] = __float2half(0.0f);
        ar1[DIN + 48 + lane] = __float2half(0.0f);
    }
}

// -------------------------------------------------------- main GEMM
// out[TOK, DOUT] = A_ext @ B_extᵀ via mma.sync.m16n8k16 (fp16 in, fp32 acc).
// 128 threads = 4 warps (2x2 of 64x64 warptiles), 2 CTAs/SM.
// Rotated pipeline: the stage-boundary wait_group+syncthreads sits before the
// LAST MMA block of each iteration, and the next stage's kh=0 fragments are
// preloaded there — the final 32-MMA burst hides the sync + ldsm latency.
__global__ void __launch_bounds__(128, 2) qlora_gemm(float* __restrict__ out) {
    extern __shared__ char smem[];
    uint32_t sb = s2u(smem);
    int tid = threadIdx.x, wid = tid >> 5, lane = tid & 31;
    int warp_m = wid & 1, warp_n = wid >> 1;   // 2 x 2

    // L2-banded CTA order: 8 m-tiles x 32 n-tiles per band (256 CTAs/band)
    int bid = (int)blockIdx.x;
    int band = bid >> 8;
    int local = bid & 255;
    int mt = band * 8 + (local & 7);   // 0..63
    int nt = local >> 3;               // 0..31

    // cp.async: 128 threads, 8 x 16B chunks per row-group of 16 rows
    const __half* sA0 = g_A + (size_t)mt * BM * K_EXT +
                        (size_t)(tid >> 3) * K_EXT + (tid & 7) * 8;
    const __half* sB0 = g_B + (size_t)nt * BN * K_EXT +
                        (size_t)(tid >> 3) * K_EXT + (tid & 7) * 8;
    uint32_t dA0 = (uint32_t)(tid >> 3) * ROWB + (tid & 7) * 16;
    uint32_t dB0 = A_BYTES + dA0;

    uint32_t aLdBase = (warp_m * 64 + (lane & 15)) * ROWB + (lane >> 4) * 16;
    uint32_t bLdBase = A_BYTES +
        (warp_n * 64 + ((lane >> 4) & 1) * 8 + (lane & 7)) * ROWB +
        ((lane >> 3) & 1) * 16;

    float acc[4][8][4];
#pragma unroll
    for (int mi = 0; mi < 4; mi++)
#pragma unroll
        for (int ni = 0; ni < 8; ni++)
#pragma unroll
            for (int j = 0; j < 4; j++) acc[mi][ni][j] = 0.0f;

#define ISSUE_STAGE(stage, kiter)                                              \
    {                                                                          \
        uint32_t base_ = sb + (stage) * STAGE_BYTES;                           \
        int k0_ = (kiter) * BK;                                                \
        _Pragma("unroll")                                                      \
        for (int i = 0; i < 8; i++)                                            \
            cp16(base_ + dA0 + i * (16 * ROWB),                                \
                 sA0 + k0_ + (size_t)i * 16 * K_EXT);                          \
        _Pragma("unroll")                                                      \
        for (int i = 0; i < 8; i++)                                            \
            cp16(base_ + dB0 + i * (16 * ROWB),                                \
                 sB0 + k0_ + (size_t)i * 16 * K_EXT);                          \
    }

    // Chunk ch (0..3): A row-groups {2ch, 2ch+1} + B row-groups {2ch, 2ch+1}
#define ISSUE_CHUNK(stage, kiter, ch)                                          \
    {                                                                          \
        uint32_t base_ = sb + (stage) * STAGE_BYTES;                           \
        int k0_ = (kiter) * BK;                                                \
        _Pragma("unroll")                                                      \
        for (int i = 2 * (ch); i < 2 * (ch) + 2; i++) {                        \
            cp16(base_ + dA0 + i * (16 * ROWB),                                \
                 sA0 + k0_ + (size_t)i * 16 * K_EXT);                          \
            cp16(base_ + dB0 + i * (16 * ROWB),                                \
                 sB0 + k0_ + (size_t)i * 16 * K_EXT);                          \
        }                                                                      \
    }

#define LOAD_FRAGS(buf, aB, bB, kOff)                                          \
    {                                                                          \
        _Pragma("unroll")                                                      \
        for (int mi = 0; mi < 4; mi++)                                         \
            ldsm4((aB) + mi * (16 * ROWB) + (kOff),                            \
                  a[buf][mi][0], a[buf][mi][1], a[buf][mi][2], a[buf][mi][3]); \
        _Pragma("unroll")                                                      \
        for (int nj = 0; nj < 4; nj++)                                         \
            ldsm4((bB) + nj * (16 * ROWB) + (kOff),                            \
                  b[buf][2 * nj][0], b[buf][2 * nj][1],                        \
                  b[buf][2 * nj + 1][0], b[buf][2 * nj + 1][1]);               \
    }

#define MMA_BLOCK(buf)                                                         \
    {                                                                          \
        _Pragma("unroll")                                                      \
        for (int mi = 0; mi < 4; mi++)                                         \
            _Pragma("unroll")                                                  \
            for (int ni = 0; ni < 8; ni++)                                     \
                mma16816(acc[mi][ni], a[buf][mi], b[buf][ni]);                 \
    }

    // ---- prologue: fill 2 stages, preload iter-0 kh=0 fragments ----
    ISSUE_STAGE(0, 0); cp_commit();
    ISSUE_STAGE(1, 1); cp_commit();

    uint32_t a[2][4][4], b[2][8][2];
    asm volatile("cp.async.wait_group %0;" :: "n"(1) : "memory");
    __syncthreads();
    LOAD_FRAGS(0, sb + aLdBase, sb + bLdBase, 0);

    int s = 0, sn = 2;
    for (int it = 0; it < KITER; ++it) {
        uint32_t aB = sb + s * STAGE_BYTES + aLdBase;
        uint32_t bB = sb + s * STAGE_BYTES + bLdBase;
        bool pf = (it + 2 < KITER);

#pragma unroll
        for (int kh = 0; kh < 4; kh++) {      // four k16 steps per BK=64
            int cur = kh & 1, nxb = cur ^ 1;
            if (kh < 3) {
                LOAD_FRAGS(nxb, aB, bB, (kh + 1) * 32);
                if (pf) { ISSUE_CHUNK(sn, it + 2, kh); }
                MMA_BLOCK(cur);
            } else {
                // rotated stage boundary: sync + next-stage kh=0 preload are
                // hidden under the final MMA block below
                if (pf) { ISSUE_CHUNK(sn, it + 2, 3); }
                cp_commit();
                asm volatile("cp.async.wait_group %0;" :: "n"(1) : "memory");
                __syncthreads();
                if (it + 1 < KITER) {
                    int s1 = (s == 2) ? 0 : s + 1;
                    uint32_t aB2 = sb + s1 * STAGE_BYTES + aLdBase;
                    uint32_t bB2 = sb + s1 * STAGE_BYTES + bLdBase;
                    LOAD_FRAGS(nxb, aB2, bB2, 0);   // nxb == 0 here
                }
                MMA_BLOCK(cur);
            }
        }

        s = (s == 2) ? 0 : s + 1;
        sn = (sn == 2) ? 0 : sn + 1;
    }

    // ---- epilogue: registers -> global fp32 ----
    int m0 = mt * BM + warp_m * 64 + (lane >> 2);
    int n0 = nt * BN + warp_n * 64 + (lane & 3) * 2;
#pragma unroll
    for (int mi = 0; mi < 4; mi++) {
#pragma unroll
        for (int ni = 0; ni < 8; ni++) {
            float* p0 = out + (size_t)(m0 + mi * 16) * DOUT + n0 + ni * 8;
            float* p1 = p0 + 8 * DOUT;
            *(float2*)p0 = make_float2(acc[mi][ni][0], acc[mi][ni][1]);
            *(float2*)p1 = make_float2(acc[mi][ni][2], acc[mi][ni][3]);
        }
    }
}

// -------------------------------------------------------- launch
extern "C" void kernel_launch(void* const* d_in, const int* in_sizes, int n_in,
                              void* d_out, int out_size) {
    const float* x = (const float*)d_in[0];
    const int* wc = (const int*)d_in[1];
    const float* am = (const float*)d_in[2];
    const float* bias = (const float*)d_in[3];
    const float* la = (const float*)d_in[4];
    const float* lb = (const float*)d_in[5];
    float* out = (float*)d_out;

    cudaFuncSetAttribute(qlora_gemm, cudaFuncAttributeMaxDynamicSharedMemorySize,
                         SMEM_TOTAL);

    prep_all<<<DOUT + TOK / 16, 256>>>(x, wc, am, bias, la, lb);
    qlora_gemm<<<MT_TILES * NT_TILES, 128, SMEM_TOTAL>>>(out);
}

// round 10
// speedup vs baseline: 1.3911x; 1.0813x over previous
#include <cuda_runtime.h>
#include <cuda_fp16.h>
#include <cstdint>
#include <cstddef>

#define TOK 8192
#define DIN 4096
#define DOUT 4096
#define RANK 16
#define NBLK (DIN / 64)
#define K_EXT 4160            // DIN + 64 (16 lora cols + 1 bias col + pad)
#define SCALING 4.0f          // 16 / sqrt(16)

#define BM 128
#define BN 128
#define BK 64
#define NSTAGE 3
#define KITER (K_EXT / BK)    // 65

#define ROWB 144                             // 128B data + 16B pad; conflict-free ldmatrix
#define A_BYTES (BM * ROWB)                  // 18432
#define B_BYTES (BN * ROWB)                  // 18432
#define STAGE_BYTES (A_BYTES + B_BYTES)      // 36864
#define SMEM_TOTAL (NSTAGE * STAGE_BYTES)    // 110592 -> 2 CTAs/SM

#define NT_TILES (DOUT / BN)                 // 32
#define MT_TILES (TOK / BM)                  // 64

#define NXU (TOK / 32)                       // 256 xu blocks (32 rows each)

// Extended operand buffers (static device scratch; no runtime allocation)
__device__ __align__(1024) __half g_A[(size_t)TOK * K_EXT];   // ~68 MB
__device__ __align__(1024) __half g_B[(size_t)DOUT * K_EXT];  // ~34 MB

__constant__ float c_nf4[16] = {
    -1.0f, -0.6961928009986877f, -0.5250730514526367f, -0.39491748809814453f,
    -0.28444138169288635f, -0.18477343022823334f, -0.09105003625154495f, 0.0f,
    0.07958029955625534f, 0.16093020141124725f, 0.24611230194568634f,
    0.33791524171829224f, 0.44070982933044434f, 0.5626170039176941f,
    0.7229568362236023f, 1.0f};

// ---------------------------------------------------------------- helpers
__device__ __forceinline__ uint32_t s2u(const void* p) {
    uint32_t a;
    asm("{ .reg .u64 t; cvta.to.shared.u64 t, %1; cvt.u32.u64 %0, t; }"
        : "=r"(a) : "l"(p));
    return a;
}
__device__ __forceinline__ void cp16(uint32_t s, const void* g) {
    asm volatile("cp.async.cg.shared.global [%0], [%1], 16;" :: "r"(s), "l"(g));
}
__device__ __forceinline__ void cp_commit() {
    asm volatile("cp.async.commit_group;" ::: "memory");
}
__device__ __forceinline__ void ldsm4(uint32_t addr, uint32_t& r0, uint32_t& r1,
                                      uint32_t& r2, uint32_t& r3) {
    asm volatile("ldmatrix.sync.aligned.m8n8.x4.shared.b16 {%0,%1,%2,%3}, [%4];"
                 : "=r"(r0), "=r"(r1), "=r"(r2), "=r"(r3) : "r"(addr));
}
__device__ __forceinline__ void mma16816(float* c, const uint32_t* a,
                                         const uint32_t* b) {
    asm volatile(
        "mma.sync.aligned.m16n8k16.row.col.f32.f16.f16.f32 "
        "{%0,%1,%2,%3}, {%4,%5,%6,%7}, {%8,%9}, {%0,%1,%2,%3};"
        : "+f"(c[0]), "+f"(c[1]), "+f"(c[2]), "+f"(c[3])
        : "r"(a[0]), "r"(a[1]), "r"(a[2]), "r"(a[3]), "r"(b[0]), "r"(b[1]));
}

// -------------------------------------------------------- fused prep kernel
// blocks [0, NXU): x -> fp16 g_A + u = x@lora_A (4 rows/warp, 32 rows/block).
//   Launched FIRST so the long xu blocks overlap the w blocks' wave.
// blocks [NXU, NXU + DOUT): NF4 dequant -> g_B (+ lora_B cols, bias, zeros)
__global__ void __launch_bounds__(256) prep_all(
    const float* __restrict__ x, const int* __restrict__ wc,
    const float* __restrict__ am, const float* __restrict__ bias,
    const float* __restrict__ la, const float* __restrict__ lb) {
    // Transposed lora_A chunk: sA2[r][kk], kk in [0,512). Consumption loads are
    // lane-consecutive float4 within one r-row -> conflict-free LDS.128.
    __shared__ float sA2[16][520];  // ~33 KB
    int tid = threadIdx.x;
    int lane = tid & 31;

    if (blockIdx.x >= NXU) {
        // ---------------- prep_w path ----------------
        // Register LUT + shfl: codebook lookup = 1 shfl.idx, no const-cache replay
        float lutv = c_nf4[lane & 15];
        int n = blockIdx.x - NXU;
        const int* wr = wc + (size_t)n * DIN;
        __half* br = g_B + (size_t)n * K_EXT;
        const float* amr = am + (size_t)n * NBLK;
        for (int k4 = tid; k4 < DIN / 4; k4 += 256) {
            int k = k4 * 4;
            int4 c = ((const int4*)wr)[k4];
            float s = amr[k >> 6];
            float v0 = __shfl_sync(0xffffffffu, lutv, c.x & 15);
            float v1 = __shfl_sync(0xffffffffu, lutv, c.y & 15);
            float v2 = __shfl_sync(0xffffffffu, lutv, c.z & 15);
            float v3 = __shfl_sync(0xffffffffu, lutv, c.w & 15);
            __half2 h0 = __floats2half2_rn(v0 * s, v1 * s);
            __half2 h1 = __floats2half2_rn(v2 * s, v3 * s);
            ((__half2*)br)[k4 * 2] = h0;
            ((__half2*)br)[k4 * 2 + 1] = h1;
        }
        if (tid < RANK) br[DIN + tid] = __float2half(SCALING * lb[(size_t)tid * DOUT + n]);
        else if (tid == RANK) br[DIN + RANK] = __float2half(bias[n]);
        else if (tid < 64) br[DIN + tid] = __float2half(0.0f);
        return;
    }

    // ------------- prep_xu path: 32 rows/block, 4 rows per warp -------------
    int wid = tid >> 5;
    size_t m0 = (size_t)blockIdx.x * 32 + wid * 4;
    const float* xr[4];
    __half* ar[4];
#pragma unroll
    for (int r = 0; r < 4; r++) {
        xr[r] = x + (m0 + r) * DIN;
        ar[r] = g_A + (m0 + r) * K_EXT;
    }
    float acc[4][16];
#pragma unroll
    for (int r = 0; r < 4; r++)
#pragma unroll
        for (int q = 0; q < 16; q++) acc[r][q] = 0.0f;

    for (int kc = 0; kc < DIN; kc += 512) {
        __syncthreads();
        const float4* la4 = (const float4*)(la + (size_t)kc * 16);
        for (int i = tid; i < 2048; i += 256) {
            float4 v = la4[i];
            int kk = i >> 2, r0 = (i & 3) * 4;
            sA2[r0][kk] = v.x;
            sA2[r0 + 1][kk] = v.y;
            sA2[r0 + 2][kk] = v.z;
            sA2[r0 + 3][kk] = v.w;
        }
        __syncthreads();
#pragma unroll
        for (int ki = 0; ki < 4; ki++) {     // 4 quads of 128 k per 512-chunk
            int k = ki * 128 + lane * 4;
            float xs[4][4];
#pragma unroll
            for (int r = 0; r < 4; r++) {
                float4 v = *(const float4*)(xr[r] + kc + k);
                xs[r][0] = v.x; xs[r][1] = v.y; xs[r][2] = v.z; xs[r][3] = v.w;
                __half2 h0 = __floats2half2_rn(v.x, v.y);
                __half2 h1 = __floats2half2_rn(v.z, v.w);
                uint2 st;
                st.x = *(uint32_t*)&h0;
                st.y = *(uint32_t*)&h1;
                *(uint2*)(ar[r] + kc + k) = st;
            }
#pragma unroll
            for (int q = 0; q < 16; q++) {
                float4 pv = *(const float4*)&sA2[q][k];
#pragma unroll
                for (int r = 0; r < 4; r++)
                    acc[r][q] += xs[r][0] * pv.x + xs[r][1] * pv.y +
                                 xs[r][2] * pv.z + xs[r][3] * pv.w;
            }
        }
    }
#pragma unroll
    for (int r = 0; r < 4; r++)
#pragma unroll
        for (int q = 0; q < 16; q++) {
            acc[r][q] += __shfl_xor_sync(0xffffffffu, acc[r][q], 16);
            acc[r][q] += __shfl_xor_sync(0xffffffffu, acc[r][q], 8);
            acc[r][q] += __shfl_xor_sync(0xffffffffu, acc[r][q], 4);
            acc[r][q] += __shfl_xor_sync(0xffffffffu, acc[r][q], 2);
            acc[r][q] += __shfl_xor_sync(0xffffffffu, acc[r][q], 1);
        }
#pragma unroll
    for (int r = 0; r < 4; r++) {
        if (lane == 0) {
#pragma unroll
            for (int q = 0; q < 16; q++) ar[r][DIN + q] = __float2half(acc[r][q]);
        }
        ar[r][DIN + 16 + lane] = __float2half(lane == 0 ? 1.0f : 0.0f);
        if (lane < 16) ar[r][DIN + 48 + lane] = __float2half(0.0f);
    }
}

// -------------------------------------------------------- main GEMM
// out[TOK, DOUT] = A_ext @ B_extᵀ via mma.sync.m16n8k16 (fp16 in, fp32 acc).
// 128 threads = 4 warps (2x2 of 64x64 warptiles), 2 CTAs/SM.
// Rotated pipeline: the stage-boundary wait_group+syncthreads sits before the
// LAST MMA block of each iteration, and the next stage's kh=0 fragments are
// preloaded there — the final 32-MMA burst hides the sync + ldsm latency.
__global__ void __launch_bounds__(128, 2) qlora_gemm(float* __restrict__ out) {
    extern __shared__ char smem[];
    uint32_t sb = s2u(smem);
    int tid = threadIdx.x, wid = tid >> 5, lane = tid & 31;
    int warp_m = wid & 1, warp_n = wid >> 1;   // 2 x 2

    // L2-banded CTA order: 8 m-tiles x 32 n-tiles per band (256 CTAs/band)
    int bid = (int)blockIdx.x;
    int band = bid >> 8;
    int local = bid & 255;
    int mt = band * 8 + (local & 7);   // 0..63
    int nt = local >> 3;               // 0..31

    // cp.async: 128 threads, 8 x 16B chunks per row-group of 16 rows
    const __half* sA0 = g_A + (size_t)mt * BM * K_EXT +
                        (size_t)(tid >> 3) * K_EXT + (tid & 7) * 8;
    const __half* sB0 = g_B + (size_t)nt * BN * K_EXT +
                        (size_t)(tid >> 3) * K_EXT + (tid & 7) * 8;
    uint32_t dA0 = (uint32_t)(tid >> 3) * ROWB + (tid & 7) * 16;
    uint32_t dB0 = A_BYTES + dA0;

    uint32_t aLdBase = (warp_m * 64 + (lane & 15)) * ROWB + (lane >> 4) * 16;
    uint32_t bLdBase = A_BYTES +
        (warp_n * 64 + ((lane >> 4) & 1) * 8 + (lane & 7)) * ROWB +
        ((lane >> 3) & 1) * 16;

    float acc[4][8][4];
#pragma unroll
    for (int mi = 0; mi < 4; mi++)
#pragma unroll
        for (int ni = 0; ni < 8; ni++)
#pragma unroll
            for (int j = 0; j < 4; j++) acc[mi][ni][j] = 0.0f;

#define ISSUE_STAGE(stage, kiter)                                              \
    {                                                                          \
        uint32_t base_ = sb + (stage) * STAGE_BYTES;                           \
        int k0_ = (kiter) * BK;                                                \
        _Pragma("unroll")                                                      \
        for (int i = 0; i < 8; i++)                                            \
            cp16(base_ + dA0 + i * (16 * ROWB),                                \
                 sA0 + k0_ + (size_t)i * 16 * K_EXT);                          \
        _Pragma("unroll")                                                      \
        for (int i = 0; i < 8; i++)                                            \
            cp16(base_ + dB0 + i * (16 * ROWB),                                \
                 sB0 + k0_ + (size_t)i * 16 * K_EXT);                          \
    }

    // Chunk ch (0..3): A row-groups {2ch, 2ch+1} + B row-groups {2ch, 2ch+1}
#define ISSUE_CHUNK(stage, kiter, ch)                                          \
    {                                                                          \
        uint32_t base_ = sb + (stage) * STAGE_BYTES;                           \
        int k0_ = (kiter) * BK;                                                \
        _Pragma("unroll")                                                      \
        for (int i = 2 * (ch); i < 2 * (ch) + 2; i++) {                        \
            cp16(base_ + dA0 + i * (16 * ROWB),                                \
                 sA0 + k0_ + (size_t)i * 16 * K_EXT);                          \
            cp16(base_ + dB0 + i * (16 * ROWB),                                \
                 sB0 + k0_ + (size_t)i * 16 * K_EXT);                          \
        }                                                                      \
    }

#define LOAD_FRAGS(buf, aB, bB, kOff)                                          \
    {                                                                          \
        _Pragma("unroll")                                                      \
        for (int mi = 0; mi < 4; mi++)                                         \
            ldsm4((aB) + mi * (16 * ROWB) + (kOff),                            \
                  a[buf][mi][0], a[buf][mi][1], a[buf][mi][2], a[buf][mi][3]); \
        _Pragma("unroll")                                                      \
        for (int nj = 0; nj < 4; nj++)                                         \
            ldsm4((bB) + nj * (16 * ROWB) + (kOff),                            \
                  b[buf][2 * nj][0], b[buf][2 * nj][1],                        \
                  b[buf][2 * nj + 1][0], b[buf][2 * nj + 1][1]);               \
    }

#define MMA_BLOCK(buf)                                                         \
    {                                                                          \
        _Pragma("unroll")                                                      \
        for (int mi = 0; mi < 4; mi++)                                         \
            _Pragma("unroll")                                                  \
            for (int ni = 0; ni < 8; ni++)                                     \
                mma16816(acc[mi][ni], a[buf][mi], b[buf][ni]);                 \
    }

    // ---- prologue: fill 2 stages, preload iter-0 kh=0 fragments ----
    ISSUE_STAGE(0, 0); cp_commit();
    ISSUE_STAGE(1, 1); cp_commit();

    uint32_t a[2][4][4], b[2][8][2];
    asm volatile("cp.async.wait_group %0;" :: "n"(1) : "memory");
    __syncthreads();
    LOAD_FRAGS(0, sb + aLdBase, sb + bLdBase, 0);

    int s = 0, sn = 2;
    for (int it = 0; it < KITER; ++it) {
        uint32_t aB = sb + s * STAGE_BYTES + aLdBase;
        uint32_t bB = sb + s * STAGE_BYTES + bLdBase;
        bool pf = (it + 2 < KITER);

#pragma unroll
        for (int kh = 0; kh < 4; kh++) {      // four k16 steps per BK=64
            int cur = kh & 1, nxb = cur ^ 1;
            if (kh < 3) {
                LOAD_FRAGS(nxb, aB, bB, (kh + 1) * 32);
                if (pf) { ISSUE_CHUNK(sn, it + 2, kh); }
                MMA_BLOCK(cur);
            } else {
                // rotated stage boundary: sync + next-stage kh=0 preload are
                // hidden under the final MMA block below
                if (pf) { ISSUE_CHUNK(sn, it + 2, 3); }
                cp_commit();
                asm volatile("cp.async.wait_group %0;" :: "n"(1) : "memory");
                __syncthreads();
                if (it + 1 < KITER) {
                    int s1 = (s == 2) ? 0 : s + 1;
                    uint32_t aB2 = sb + s1 * STAGE_BYTES + aLdBase;
                    uint32_t bB2 = sb + s1 * STAGE_BYTES + bLdBase;
                    LOAD_FRAGS(nxb, aB2, bB2, 0);   // nxb == 0 here
                }
                MMA_BLOCK(cur);
            }
        }

        s = (s == 2) ? 0 : s + 1;
        sn = (sn == 2) ? 0 : sn + 1;
    }

    // ---- epilogue: registers -> global fp32 ----
    int m0 = mt * BM + warp_m * 64 + (lane >> 2);
    int n0 = nt * BN + warp_n * 64 + (lane & 3) * 2;
#pragma unroll
    for (int mi = 0; mi < 4; mi++) {
#pragma unroll
        for (int ni = 0; ni < 8; ni++) {
            float* p0 = out + (size_t)(m0 + mi * 16) * DOUT + n0 + ni * 8;
            float* p1 = p0 + 8 * DOUT;
            *(float2*)p0 = make_float2(acc[mi][ni][0], acc[mi][ni][1]);
            *(float2*)p1 = make_float2(acc[mi][ni][2], acc[mi][ni][3]);
        }
    }
}

// -------------------------------------------------------- launch
extern "C" void kernel_launch(void* const* d_in, const int* in_sizes, int n_in,
                              void* d_out, int out_size) {
    const float* x = (const float*)d_in[0];
    const int* wc = (const int*)d_in[1];
    const float* am = (const float*)d_in[2];
    const float* bias = (const float*)d_in[3];
    const float* la = (const float*)d_in[4];
    const float* lb = (const float*)d_in[5];
    float* out = (float*)d_out;

    cudaFuncSetAttribute(qlora_gemm, cudaFuncAttributeMaxDynamicSharedMemorySize,
                         SMEM_TOTAL);

    prep_all<<<NXU + DOUT, 256>>>(x, wc, am, bias, la, lb);
    qlora_gemm<<<MT_TILES * NT_TILES, 128, SMEM_TOTAL>>>(out);
}

// round 11
// speedup vs baseline: 1.3930x; 1.0014x over previous
#include <cuda_runtime.h>
#include <cuda_fp16.h>
#include <cstdint>
#include <cstddef>

#define TOK 8192
#define DIN 4096
#define DOUT 4096
#define RANK 16
#define NBLK (DIN / 64)
#define K_EXT 4160            // DIN + 64 (16 lora cols + 1 bias col + pad)
#define SCALING 4.0f          // 16 / sqrt(16)

#define BM 128
#define BN 128
#define BK 64
#define NSTAGE 3
#define KITER (K_EXT / BK)    // 65

#define ROWB 144                             // 128B data + 16B pad; conflict-free ldmatrix
#define A_BYTES (BM * ROWB)                  // 18432
#define B_BYTES (BN * ROWB)                  // 18432
#define STAGE_BYTES (A_BYTES + B_BYTES)      // 36864
#define SMEM_TOTAL (NSTAGE * STAGE_BYTES)    // 110592 -> 2 CTAs/SM

#define NT_TILES (DOUT / BN)                 // 32
#define MT_TILES (TOK / BM)                  // 64

#define NXU (TOK / 32)                       // 256 xu blocks (32 rows each)

// Extended operand buffers (static device scratch; no runtime allocation)
__device__ __align__(1024) __half g_A[(size_t)TOK * K_EXT];   // ~68 MB
__device__ __align__(1024) __half g_B[(size_t)DOUT * K_EXT];  // ~34 MB

__constant__ float c_nf4[16] = {
    -1.0f, -0.6961928009986877f, -0.5250730514526367f, -0.39491748809814453f,
    -0.28444138169288635f, -0.18477343022823334f, -0.09105003625154495f, 0.0f,
    0.07958029955625534f, 0.16093020141124725f, 0.24611230194568634f,
    0.33791524171829224f, 0.44070982933044434f, 0.5626170039176941f,
    0.7229568362236023f, 1.0f};

// ---------------------------------------------------------------- helpers
__device__ __forceinline__ uint32_t s2u(const void* p) {
    uint32_t a;
    asm("{ .reg .u64 t; cvta.to.shared.u64 t, %1; cvt.u32.u64 %0, t; }"
        : "=r"(a) : "l"(p));
    return a;
}
__device__ __forceinline__ void cp16(uint32_t s, const void* g) {
    asm volatile("cp.async.cg.shared.global [%0], [%1], 16;" :: "r"(s), "l"(g));
}
__device__ __forceinline__ void cp_commit() {
    asm volatile("cp.async.commit_group;" ::: "memory");
}
__device__ __forceinline__ void ldsm4(uint32_t addr, uint32_t& r0, uint32_t& r1,
                                      uint32_t& r2, uint32_t& r3) {
    asm volatile("ldmatrix.sync.aligned.m8n8.x4.shared.b16 {%0,%1,%2,%3}, [%4];"
                 : "=r"(r0), "=r"(r1), "=r"(r2), "=r"(r3) : "r"(addr));
}
__device__ __forceinline__ void mma16816(float* c, const uint32_t* a,
                                         const uint32_t* b) {
    asm volatile(
        "mma.sync.aligned.m16n8k16.row.col.f32.f16.f16.f32 "
        "{%0,%1,%2,%3}, {%4,%5,%6,%7}, {%8,%9}, {%0,%1,%2,%3};"
        : "+f"(c[0]), "+f"(c[1]), "+f"(c[2]), "+f"(c[3])
        : "r"(a[0]), "r"(a[1]), "r"(a[2]), "r"(a[3]), "r"(b[0]), "r"(b[1]));
}

// -------------------------------------------------------- fused prep kernel
// blocks [0, NXU): x -> fp16 g_A + u = x@lora_A (4 rows/warp, 32 rows/block).
//   Launched FIRST so the long xu blocks overlap the w blocks' wave.
// blocks [NXU, NXU + DOUT): NF4 dequant -> g_B (+ lora_B cols, bias, zeros)
__global__ void __launch_bounds__(256) prep_all(
    const float* __restrict__ x, const int* __restrict__ wc,
    const float* __restrict__ am, const float* __restrict__ bias,
    const float* __restrict__ la, const float* __restrict__ lb) {
    // Transposed lora_A chunk: sA2[r][kk], kk in [0,512). Consumption loads are
    // lane-consecutive float4 within one r-row -> conflict-free LDS.128.
    __shared__ float sA2[16][520];  // ~33 KB
    int tid = threadIdx.x;
    int lane = tid & 31;

    if (blockIdx.x >= NXU) {
        // ---------------- prep_w path ----------------
        // Register LUT + shfl: codebook lookup = 1 shfl.idx, no const-cache replay
        float lutv = c_nf4[lane & 15];
        int n = blockIdx.x - NXU;
        const int* wr = wc + (size_t)n * DIN;
        __half* br = g_B + (size_t)n * K_EXT;
        const float* amr = am + (size_t)n * NBLK;
        for (int k4 = tid; k4 < DIN / 4; k4 += 256) {
            int k = k4 * 4;
            int4 c = ((const int4*)wr)[k4];
            float s = amr[k >> 6];
            float v0 = __shfl_sync(0xffffffffu, lutv, c.x & 15);
            float v1 = __shfl_sync(0xffffffffu, lutv, c.y & 15);
            float v2 = __shfl_sync(0xffffffffu, lutv, c.z & 15);
            float v3 = __shfl_sync(0xffffffffu, lutv, c.w & 15);
            __half2 h0 = __floats2half2_rn(v0 * s, v1 * s);
            __half2 h1 = __floats2half2_rn(v2 * s, v3 * s);
            ((__half2*)br)[k4 * 2] = h0;
            ((__half2*)br)[k4 * 2 + 1] = h1;
        }
        if (tid < RANK) br[DIN + tid] = __float2half(SCALING * lb[(size_t)tid * DOUT + n]);
        else if (tid == RANK) br[DIN + RANK] = __float2half(bias[n]);
        else if (tid < 64) br[DIN + tid] = __float2half(0.0f);
        return;
    }

    // ------------- prep_xu path: 32 rows/block, 4 rows per warp -------------
    int wid = tid >> 5;
    size_t m0 = (size_t)blockIdx.x * 32 + wid * 4;
    const float* xr[4];
    __half* ar[4];
#pragma unroll
    for (int r = 0; r < 4; r++) {
        xr[r] = x + (m0 + r) * DIN;
        ar[r] = g_A + (m0 + r) * K_EXT;
    }
    float acc[4][16];
#pragma unroll
    for (int r = 0; r < 4; r++)
#pragma unroll
        for (int q = 0; q < 16; q++) acc[r][q] = 0.0f;

    for (int kc = 0; kc < DIN; kc += 512) {
        __syncthreads();
        const float4* la4 = (const float4*)(la + (size_t)kc * 16);
        for (int i = tid; i < 2048; i += 256) {
            float4 v = la4[i];
            int kk = i >> 2, r0 = (i & 3) * 4;
            sA2[r0][kk] = v.x;
            sA2[r0 + 1][kk] = v.y;
            sA2[r0 + 2][kk] = v.z;
            sA2[r0 + 3][kk] = v.w;
        }
        __syncthreads();
#pragma unroll
        for (int ki = 0; ki < 4; ki++) {     // 4 quads of 128 k per 512-chunk
            int k = ki * 128 + lane * 4;
            float xs[4][4];
#pragma unroll
            for (int r = 0; r < 4; r++) {
                float4 v = *(const float4*)(xr[r] + kc + k);
                xs[r][0] = v.x; xs[r][1] = v.y; xs[r][2] = v.z; xs[r][3] = v.w;
                __half2 h0 = __floats2half2_rn(v.x, v.y);
                __half2 h1 = __floats2half2_rn(v.z, v.w);
                uint2 st;
                st.x = *(uint32_t*)&h0;
                st.y = *(uint32_t*)&h1;
                *(uint2*)(ar[r] + kc + k) = st;
            }
#pragma unroll
            for (int q = 0; q < 16; q++) {
                float4 pv = *(const float4*)&sA2[q][k];
#pragma unroll
                for (int r = 0; r < 4; r++)
                    acc[r][q] += xs[r][0] * pv.x + xs[r][1] * pv.y +
                                 xs[r][2] * pv.z + xs[r][3] * pv.w;
            }
        }
    }
#pragma unroll
    for (int r = 0; r < 4; r++)
#pragma unroll
        for (int q = 0; q < 16; q++) {
            acc[r][q] += __shfl_xor_sync(0xffffffffu, acc[r][q], 16);
            acc[r][q] += __shfl_xor_sync(0xffffffffu, acc[r][q], 8);
            acc[r][q] += __shfl_xor_sync(0xffffffffu, acc[r][q], 4);
            acc[r][q] += __shfl_xor_sync(0xffffffffu, acc[r][q], 2);
            acc[r][q] += __shfl_xor_sync(0xffffffffu, acc[r][q], 1);
        }
#pragma unroll
    for (int r = 0; r < 4; r++) {
        if (lane == 0) {
#pragma unroll
            for (int q = 0; q < 16; q++) ar[r][DIN + q] = __float2half(acc[r][q]);
        }
        ar[r][DIN + 16 + lane] = __float2half(lane == 0 ? 1.0f : 0.0f);
        if (lane < 16) ar[r][DIN + 48 + lane] = __float2half(0.0f);
    }
}

// -------------------------------------------------------- main GEMM
// out[TOK, DOUT] = A_ext @ B_extᵀ via mma.sync.m16n8k16 (fp16 in, fp32 acc).
// 128 threads = 4 warps (2x2 of 64x64 warptiles), 2 CTAs/SM.
// Rotated pipeline + anti-aligned co-resident CTAs: odd CTAs start the main
// loop half an iteration late, so one CTA's MMA burst covers the other's
// stage-boundary sync bubble (identical periods keep them anti-aligned).
__global__ void __launch_bounds__(128, 2) qlora_gemm(float* __restrict__ out) {
    extern __shared__ char smem[];
    uint32_t sb = s2u(smem);
    int tid = threadIdx.x, wid = tid >> 5, lane = tid & 31;
    int warp_m = wid & 1, warp_n = wid >> 1;   // 2 x 2

    // L2-banded CTA order: 8 m-tiles x 32 n-tiles per band (256 CTAs/band)
    int bid = (int)blockIdx.x;
    int band = bid >> 8;
    int local = bid & 255;
    int mt = band * 8 + (local & 7);   // 0..63
    int nt = local >> 3;               // 0..31

    // cp.async: 128 threads, 8 x 16B chunks per row-group of 16 rows
    const __half* sA0 = g_A + (size_t)mt * BM * K_EXT +
                        (size_t)(tid >> 3) * K_EXT + (tid & 7) * 8;
    const __half* sB0 = g_B + (size_t)nt * BN * K_EXT +
                        (size_t)(tid >> 3) * K_EXT + (tid & 7) * 8;
    uint32_t dA0 = (uint32_t)(tid >> 3) * ROWB + (tid & 7) * 16;
    uint32_t dB0 = A_BYTES + dA0;

    uint32_t aLdBase = (warp_m * 64 + (lane & 15)) * ROWB + (lane >> 4) * 16;
    uint32_t bLdBase = A_BYTES +
        (warp_n * 64 + ((lane >> 4) & 1) * 8 + (lane & 7)) * ROWB +
        ((lane >> 3) & 1) * 16;

    float acc[4][8][4];
#pragma unroll
    for (int mi = 0; mi < 4; mi++)
#pragma unroll
        for (int ni = 0; ni < 8; ni++)
#pragma unroll
            for (int j = 0; j < 4; j++) acc[mi][ni][j] = 0.0f;

#define ISSUE_STAGE(stage, kiter)                                              \
    {                                                                          \
        uint32_t base_ = sb + (stage) * STAGE_BYTES;                           \
        int k0_ = (kiter) * BK;                                                \
        _Pragma("unroll")                                                      \
        for (int i = 0; i < 8; i++)                                            \
            cp16(base_ + dA0 + i * (16 * ROWB),                                \
                 sA0 + k0_ + (size_t)i * 16 * K_EXT);                          \
        _Pragma("unroll")                                                      \
        for (int i = 0; i < 8; i++)                                            \
            cp16(base_ + dB0 + i * (16 * ROWB),                                \
                 sB0 + k0_ + (size_t)i * 16 * K_EXT);                          \
    }

    // Chunk ch (0..3): A row-groups {2ch, 2ch+1} + B row-groups {2ch, 2ch+1}
#define ISSUE_CHUNK(stage, kiter, ch)                                          \
    {                                                                          \
        uint32_t base_ = sb + (stage) * STAGE_BYTES;                           \
        int k0_ = (kiter) * BK;                                                \
        _Pragma("unroll")                                                      \
        for (int i = 2 * (ch); i < 2 * (ch) + 2; i++) {                        \
            cp16(base_ + dA0 + i * (16 * ROWB),                                \
                 sA0 + k0_ + (size_t)i * 16 * K_EXT);                          \
            cp16(base_ + dB0 + i * (16 * ROWB),                                \
                 sB0 + k0_ + (size_t)i * 16 * K_EXT);                          \
        }                                                                      \
    }

#define LOAD_FRAGS(buf, aB, bB, kOff)                                          \
    {                                                                          \
        _Pragma("unroll")                                                      \
        for (int mi = 0; mi < 4; mi++)                                         \
            ldsm4((aB) + mi * (16 * ROWB) + (kOff),                            \
                  a[buf][mi][0], a[buf][mi][1], a[buf][mi][2], a[buf][mi][3]); \
        _Pragma("unroll")                                                      \
        for (int nj = 0; nj < 4; nj++)                                         \
            ldsm4((bB) + nj * (16 * ROWB) + (kOff),                            \
                  b[buf][2 * nj][0], b[buf][2 * nj][1],                        \
                  b[buf][2 * nj + 1][0], b[buf][2 * nj + 1][1]);               \
    }

    // Half an MMA block: mi in {h*2, h*2+1} -> 16 HMMA
#define MMA_HALF(buf, h)                                                       \
    {                                                                          \
        _Pragma("unroll")                                                      \
        for (int mi = 2 * (h); mi < 2 * (h) + 2; mi++)                         \
            _Pragma("unroll")                                                  \
            for (int ni = 0; ni < 8; ni++)                                     \
                mma16816(acc[mi][ni], a[buf][mi], b[buf][ni]);                 \
    }

    // ---- prologue: fill 2 stages, preload iter-0 kh=0 fragments ----
    ISSUE_STAGE(0, 0); cp_commit();
    ISSUE_STAGE(1, 1); cp_commit();

    uint32_t a[2][4][4], b[2][8][2];
    asm volatile("cp.async.wait_group %0;" :: "n"(1) : "memory");
    __syncthreads();

    // Anti-align the two co-resident CTAs: odd CTAs delay ~half an iteration
    // so their stage-boundary bubbles interleave with the partner's MMA work.
    if (bid & 1) {
        unsigned long long t0 = clock64();
        while (clock64() - t0 < 1300) { }
    }
    LOAD_FRAGS(0, sb + aLdBase, sb + bLdBase, 0);

    int s = 0, sn = 2;
    for (int it = 0; it < KITER; ++it) {
        uint32_t aB = sb + s * STAGE_BYTES + aLdBase;
        uint32_t bB = sb + s * STAGE_BYTES + bLdBase;
        bool pf = (it + 2 < KITER);

#pragma unroll
        for (int kh = 0; kh < 4; kh++) {      // four k16 steps per BK=64
            int cur = kh & 1, nxb = cur ^ 1;
            if (kh < 3) {
                LOAD_FRAGS(nxb, aB, bB, (kh + 1) * 32);
                MMA_HALF(cur, 0);
                // cp chunk issued inside the tensor shadow, between MMA halves
                if (pf) { ISSUE_CHUNK(sn, it + 2, kh); }
                MMA_HALF(cur, 1);
            } else {
                // rotated stage boundary: sync + next-stage kh=0 preload are
                // hidden under the final MMA block below
                if (pf) { ISSUE_CHUNK(sn, it + 2, 3); }
                cp_commit();
                asm volatile("cp.async.wait_group %0;" :: "n"(1) : "memory");
                __syncthreads();
                if (it + 1 < KITER) {
                    int s1 = (s == 2) ? 0 : s + 1;
                    uint32_t aB2 = sb + s1 * STAGE_BYTES + aLdBase;
                    uint32_t bB2 = sb + s1 * STAGE_BYTES + bLdBase;
                    LOAD_FRAGS(nxb, aB2, bB2, 0);   // nxb == 0 here
                }
                MMA_HALF(cur, 0);
                MMA_HALF(cur, 1);
            }
        }

        s = (s == 2) ? 0 : s + 1;
        sn = (sn == 2) ? 0 : sn + 1;
    }

    // ---- epilogue: registers -> global fp32 ----
    int m0 = mt * BM + warp_m * 64 + (lane >> 2);
    int n0 = nt * BN + warp_n * 64 + (lane & 3) * 2;
#pragma unroll
    for (int mi = 0; mi < 4; mi++) {
#pragma unroll
        for (int ni = 0; ni < 8; ni++) {
            float* p0 = out + (size_t)(m0 + mi * 16) * DOUT + n0 + ni * 8;
            float* p1 = p0 + 8 * DOUT;
            *(float2*)p0 = make_float2(acc[mi][ni][0], acc[mi][ni][1]);
            *(float2*)p1 = make_float2(acc[mi][ni][2], acc[mi][ni][3]);
        }
    }
}

// -------------------------------------------------------- launch
extern "C" void kernel_launch(void* const* d_in, const int* in_sizes, int n_in,
                              void* d_out, int out_size) {
    const float* x = (const float*)d_in[0];
    const int* wc = (const int*)d_in[1];
    const float* am = (const float*)d_in[2];
    const float* bias = (const float*)d_in[3];
    const float* la = (const float*)d_in[4];
    const float* lb = (const float*)d_in[5];
    float* out = (float*)d_out;

    cudaFuncSetAttribute(qlora_gemm, cudaFuncAttributeMaxDynamicSharedMemorySize,
                         SMEM_TOTAL);

    prep_all<<<NXU + DOUT, 256>>>(x, wc, am, bias, la, lb);
    qlora_gemm<<<MT_TILES * NT_TILES, 128, SMEM_TOTAL>>>(out);
}